// round 14
// baseline (speedup 1.0000x reference)
#include <cuda_runtime.h>
#include <math.h>

#define Sdim 2048
#define Edim 512
#define WIN  11
#define Fdim 5632            // WIN * Edim
#define NTH  128

// Packed dual-fp32 FMA: a.{x,y} += {xlo,xhi} * w   (w broadcast to both lanes)
__device__ __forceinline__ void ffma2(float2& a, float xlo, float xhi, float w) {
    asm("{\n\t.reg .b64 X, Wd, A;\n\t"
        "mov.b64 X, {%2, %3};\n\t"
        "mov.b64 Wd, {%4, %4};\n\t"
        "mov.b64 A, {%0, %1};\n\t"
        "fma.rn.f32x2 A, X, Wd, A;\n\t"
        "mov.b64 {%0, %1}, A;\n\t}"
        : "+f"(a.x), "+f"(a.y) : "f"(xlo), "f"(xhi), "f"(w));
}

__device__ __forceinline__ float tanh_fast(float v) {
    float r;
    asm("tanh.approx.f32 %0, %1;" : "=f"(r) : "f"(v));
    return r;
}

__device__ __forceinline__ void pf_l2(const void* p) {
    asm volatile("prefetch.global.L2 [%0];" :: "l"(p));
}

// One window-row chunk: W rows loaded and consumed one at a time (short live range)
__device__ __forceinline__ void stepA(const float* __restrict__ Wp, int ioff,
                                      float4 xv0, float4 xv1, float4 xv2, float4 xv3,
                                      float2 (&acc)[2][WIN]) {
    #pragma unroll
    for (int w = 0; w < WIN; w++) {
        float4 w4 = *(const float4*)(Wp + (size_t)w * Fdim + ioff);
        ffma2(acc[0][w], xv0.x, xv1.x, w4.x);
        ffma2(acc[0][w], xv0.y, xv1.y, w4.y);
        ffma2(acc[0][w], xv0.z, xv1.z, w4.z);
        ffma2(acc[0][w], xv0.w, xv1.w, w4.w);
        ffma2(acc[1][w], xv2.x, xv3.x, w4.x);
        ffma2(acc[1][w], xv2.y, xv3.y, w4.y);
        ffma2(acc[1][w], xv2.z, xv3.z, w4.z);
        ffma2(acc[1][w], xv2.w, xv3.w, w4.w);
    }
}

__global__ __launch_bounds__(NTH, 6)
void winattn_kernel(const float* __restrict__ x,
                    const float* __restrict__ W,
                    const float* __restrict__ bias,
                    float* __restrict__ out) {
    __shared__ float2 red[4][22];      // per-warp partials (2 local pairs x 11 w)
    __shared__ float2 gates[22];       // gates for this CTA's 4 batches

    const int s   = blockIdx.x >> 1;
    const int b0  = (blockIdx.x & 1) * 4;   // batches b0..b0+3
    const int tid = threadIdx.x;
    const int ex  = 4 * tid;                // float4 slot within e (0..508)

    const size_t bst = (size_t)Sdim * Edim;
    const float* Wb  = W + (size_t)s * (WIN * Fdim) + ex;
    const float* xb  = x + (size_t)b0 * bst + ex;
    const float* xr0 = xb + (size_t)(s - 5) * Edim;   // window start row (batch b0)
    const float* xr2 = xr0 + 2 * bst;                 // same row, batch b0+2
    const bool interior = (s >= 5) && (s <= Sdim - 6);

    // ---------------- Stage A: full-f gate dots for 4 batches --------------
    float2 acc[2][WIN];
    #pragma unroll
    for (int p = 0; p < 2; p++)
        #pragma unroll
        for (int w = 0; w < WIN; w++)
            acc[p][w] = make_float2(0.f, 0.f);

    if (interior) {
        #pragma unroll
        for (int i = 0; i < WIN; i++) {
            // prefetch W rows for iteration i+2 (fire-and-forget, no regs)
            if (i + 2 < WIN) {
                #pragma unroll
                for (int w = 0; w < WIN; w++)
                    pf_l2(Wb + (size_t)w * Fdim + (i + 2) * Edim);
            }
            float4 xv0 = *(const float4*)(xr0 + i * Edim);
            float4 xv1 = *(const float4*)(xr0 + i * Edim + bst);
            float4 xv2 = *(const float4*)(xr2 + i * Edim);
            float4 xv3 = *(const float4*)(xr2 + i * Edim + bst);
            stepA(Wb, i * Edim, xv0, xv1, xv2, xv3, acc);
        }
    } else {
        for (int i = 0; i < WIN; i++) {
            int row = s + i - 5;
            if ((unsigned)row >= (unsigned)Sdim) continue;
            const float* xr = xb + (size_t)row * Edim;
            float4 xv0 = *(const float4*)(xr);
            float4 xv1 = *(const float4*)(xr + bst);
            float4 xv2 = *(const float4*)(xr + 2 * bst);
            float4 xv3 = *(const float4*)(xr + 3 * bst);
            stepA(Wb, i * Edim, xv0, xv1, xv2, xv3, acc);
        }
    }

    // ---------------- reduce: warp shfl, then 4 warps via smem -------------
    float* af = (float*)acc;           // 44 floats
    #pragma unroll
    for (int off = 16; off > 0; off >>= 1) {
        #pragma unroll
        for (int i = 0; i < 44; i++)
            af[i] += __shfl_xor_sync(0xffffffffu, af[i], off);
    }
    const int lane = tid & 31, wrp = tid >> 5;
    if (lane == 0) {
        #pragma unroll
        for (int p = 0; p < 2; p++)
            #pragma unroll
            for (int w = 0; w < WIN; w++)
                red[wrp][p * WIN + w] = acc[p][w];
    }
    __syncthreads();

    if (tid < 22) {
        int p = tid / WIN;             // local pair 0..1
        int w = tid - p * WIN;
        float2 t = make_float2(0.f, 0.f);
        #pragma unroll
        for (int q = 0; q < 4; q++) {
            float2 v = red[q][tid];
            t.x += v.x;
            t.y += v.y;
        }
        float bb = bias[s * WIN + w];
        float2 gt;
        gt.x = 1.0f / (1.0f + expf(-(t.x + bb)));
        gt.y = 1.0f / (1.0f + expf(-(t.y + bb)));
        gates[tid] = gt;               // .x = batch b0+2p, .y = batch b0+2p+1
    }
    __syncthreads();

    // ---------------- Stage B: score + tanh (x via L1/L2) ------------------
    float2 a[4][2];                    // [local batch][lo/hi float2 of float4]
    #pragma unroll
    for (int q = 0; q < 4; q++) {
        a[q][0] = make_float2(0.f, 0.f);
        a[q][1] = make_float2(0.f, 0.f);
    }

    if (interior) {
        #pragma unroll
        for (int w = 0; w < WIN; w++) {
            float4 xv0 = *(const float4*)(xr0 + w * Edim);
            float4 xv1 = *(const float4*)(xr0 + w * Edim + bst);
            float4 xv2 = *(const float4*)(xr2 + w * Edim);
            float4 xv3 = *(const float4*)(xr2 + w * Edim + bst);
            float2 g0 = gates[w];
            float2 g1 = gates[WIN + w];
            ffma2(a[0][0], xv0.x, xv0.y, g0.x);
            ffma2(a[0][1], xv0.z, xv0.w, g0.x);
            ffma2(a[1][0], xv1.x, xv1.y, g0.y);
            ffma2(a[1][1], xv1.z, xv1.w, g0.y);
            ffma2(a[2][0], xv2.x, xv2.y, g1.x);
            ffma2(a[2][1], xv2.z, xv2.w, g1.x);
            ffma2(a[3][0], xv3.x, xv3.y, g1.y);
            ffma2(a[3][1], xv3.z, xv3.w, g1.y);
        }
    } else {
        for (int w = 0; w < WIN; w++) {
            int row = s + w - 5;
            if ((unsigned)row >= (unsigned)Sdim) continue;
            const float* xr = xb + (size_t)row * Edim;
            #pragma unroll
            for (int q = 0; q < 4; q++) {
                float4 xv = *(const float4*)(xr + (size_t)q * bst);
                float2 gp = gates[(q >> 1) * WIN + w];
                float g = (q & 1) ? gp.y : gp.x;
                ffma2(a[q][0], xv.x, xv.y, g);
                ffma2(a[q][1], xv.z, xv.w, g);
            }
        }
    }

    #pragma unroll
    for (int q = 0; q < 4; q++) {
        float4 o;
        o.x = tanh_fast(a[q][0].x);
        o.y = tanh_fast(a[q][0].y);
        o.z = tanh_fast(a[q][1].x);
        o.w = tanh_fast(a[q][1].y);
        *(float4*)(out + ((size_t)(b0 + q) * Sdim + s) * Edim + ex) = o;
    }
}

extern "C" void kernel_launch(void* const* d_in, const int* in_sizes, int n_in,
                              void* d_out, int out_size) {
    const float* x  = (const float*)d_in[0];
    const float* W  = (const float*)d_in[1];
    const float* bv = (const float*)d_in[2];
    float* out = (float*)d_out;

    winattn_kernel<<<2 * Sdim, NTH>>>(x, W, bv, out);
}